// round 2
// baseline (speedup 1.0000x reference)
#include <cuda_runtime.h>
#include <math.h>

#define NN 10000
#define EE 320000
#define KDIM 1024
#define JDIM 1024

// ---------------- scratch (static device globals; no allocation) ----------------
__device__ int   g_is64;
__device__ int   g_srcE[EE];
__device__ int   g_dstE[EE];
__device__ int   g_srcSorted[EE];
__device__ int   g_degi[NN];
__device__ int   g_cnt[NN];
__device__ int   g_off[NN + 1];
__device__ float g_A[(size_t)NN * KDIM];     // [aggX | X | aggH | h]
__device__ float g_W[(size_t)KDIM * JDIM];   // packed weights, row-major K x J
__device__ float g_bias[JDIM];               // bx_l + bh_l packed per output col
__device__ float g_pre[(size_t)NN * JDIM];   // GEMM output (gate preactivations)

// ---------------- edge dtype detection (int32 vs int64) ----------------
__global__ void k_detect(const unsigned* __restrict__ w) {
    unsigned bad = 0;
    #pragma unroll
    for (int i = 0; i < 64; i++) bad |= w[2 * i + 1];  // high words if int64
    g_is64 = (bad == 0) ? 1 : 0;
}

// convert edges + zero per-node counters in one pass
__global__ void k_convert(const void* __restrict__ ei) {
    int e = blockIdx.x * blockDim.x + threadIdx.x;
    if (e < NN) { g_degi[e] = 0; g_cnt[e] = 0; }
    if (e >= EE) return;
    int src, dst;
    if (g_is64) {
        const long long* p = (const long long*)ei;
        src = (int)p[e];
        dst = (int)p[EE + e];
    } else {
        const int* p = (const int*)ei;
        src = p[e];
        dst = p[EE + e];
    }
    g_srcE[e] = src;
    g_dstE[e] = dst;
}

// ---------------- CSR build ----------------
__global__ void k_hist() {
    int e = blockIdx.x * blockDim.x + threadIdx.x;
    if (e < EE) atomicAdd(&g_degi[g_dstE[e]], 1);
}

__global__ void k_scan() {
    __shared__ int s[1024];
    const int CH = (NN + 1023) / 1024;  // 10
    int t = threadIdx.x;
    int base = t * CH;
    int loc = 0;
    #pragma unroll
    for (int i = 0; i < CH; i++) {
        int idx = base + i;
        if (idx < NN) loc += g_degi[idx];
    }
    s[t] = loc;
    __syncthreads();
    for (int off = 1; off < 1024; off <<= 1) {
        int v = (t >= off) ? s[t - off] : 0;
        __syncthreads();
        s[t] += v;
        __syncthreads();
    }
    int run = s[t] - loc;  // exclusive prefix
    #pragma unroll
    for (int i = 0; i < CH; i++) {
        int idx = base + i;
        if (idx < NN) {
            g_off[idx] = run;
            run += g_degi[idx];
        }
    }
    if (t == 1023) g_off[NN] = run;
}

__global__ void k_scatter() {
    int e = blockIdx.x * blockDim.x + threadIdx.x;
    if (e >= EE) return;
    int d = g_dstE[e];
    int pos = g_off[d] + atomicAdd(&g_cnt[d], 1);
    g_srcSorted[pos] = g_srcE[e];
}

// ---------------- aggregation + A packing ----------------
__global__ __launch_bounds__(256) void k_agg(const float* __restrict__ X,
                                             const float* __restrict__ h) {
    __shared__ int sidx[128];
    int n = blockIdx.x;
    int t = threadIdx.x;  // 256 threads; feature index
    int s0 = g_off[n], s1 = g_off[n + 1];
    float sx = 0.f, sh = 0.f;
    for (int base = s0; base < s1; base += 128) {
        int cnt = min(128, s1 - base);
        if (t < cnt) sidx[t] = g_srcSorted[base + t];
        __syncthreads();
        for (int j = 0; j < cnt; j++) {
            int s = sidx[j];
            sx += X[s * 256 + t];
            sh += h[s * 256 + t];
        }
        __syncthreads();
    }
    int deg = s1 - s0;
    float inv = 1.f / (float)(deg > 0 ? deg : 1);
    size_t o = (size_t)n * 1024;
    g_A[o + t]       = sx * inv;
    g_A[o + 256 + t] = X[n * 256 + t];
    g_A[o + 512 + t] = sh * inv;
    g_A[o + 768 + t] = h[n * 256 + t];
}

// ---------------- weight packing ----------------
// A column order: [aggX | X | aggH | h]  ->  W row segments: [Wx_l | Wx_r | Wh_l | Wh_r]
// Output column j = gate*256 + e
__global__ void k_packW(const float* __restrict__ Wx_l, const float* __restrict__ Wx_r,
                        const float* __restrict__ Wh_l, const float* __restrict__ Wh_r,
                        const float* __restrict__ bx_l, const float* __restrict__ bh_l) {
    int idx = blockIdx.x * blockDim.x + threadIdx.x;
    if (idx >= KDIM * JDIM) return;
    int d = idx >> 10;        // K row
    int j = idx & 1023;       // output col
    int k = j >> 8, e = j & 255;
    int seg = d >> 8, dd = d & 255;
    const float* src = (seg == 0) ? Wx_l : (seg == 1) ? Wx_r : (seg == 2) ? Wh_l : Wh_r;
    g_W[idx] = src[k * 65536 + dd * 256 + e];
    if (idx < JDIM) g_bias[idx] = bx_l[k * 256 + e] + bh_l[k * 256 + e];
}

// ---------------- SGEMM: g_pre = g_A @ g_W + g_bias ----------------
#define BM 128
#define BN 128
#define BK 16

__global__ __launch_bounds__(256, 2) void k_sgemm() {
    __shared__ float As[BK][BM];
    __shared__ float Bs[BK][BN];
    int row0 = blockIdx.y * BM;
    int col0 = blockIdx.x * BN;
    int tid = threadIdx.x;
    int tx = tid & 15, ty = tid >> 4;

    float acc[8][8];
    #pragma unroll
    for (int i = 0; i < 8; i++)
        #pragma unroll
        for (int j = 0; j < 8; j++) acc[i][j] = 0.f;

    int am  = tid >> 1;           // A tile row 0..127
    int akq = (tid & 1) * 8;      // float offset within K-slab (0 or 8)
    int ar  = row0 + am;
    int bk  = tid >> 4;           // B tile row 0..15
    int bc  = (tid & 15) * 8;     // col offset

    for (int k0 = 0; k0 < KDIM; k0 += BK) {
        float4 a0, a1;
        if (ar < NN) {
            const float4* p = (const float4*)(g_A + (size_t)ar * KDIM + k0 + akq);
            a0 = p[0]; a1 = p[1];
        } else {
            a0 = make_float4(0.f, 0.f, 0.f, 0.f); a1 = a0;
        }
        const float4* pb = (const float4*)(g_W + (size_t)(k0 + bk) * JDIM + col0 + bc);
        float4 b0 = pb[0], b1 = pb[1];

        As[akq + 0][am] = a0.x; As[akq + 1][am] = a0.y;
        As[akq + 2][am] = a0.z; As[akq + 3][am] = a0.w;
        As[akq + 4][am] = a1.x; As[akq + 5][am] = a1.y;
        As[akq + 6][am] = a1.z; As[akq + 7][am] = a1.w;
        *(float4*)&Bs[bk][bc]     = b0;
        *(float4*)&Bs[bk][bc + 4] = b1;
        __syncthreads();

        #pragma unroll
        for (int kk = 0; kk < BK; kk++) {
            float a[8], b[8];
            *(float4*)(a)     = *(float4*)&As[kk][ty * 8];
            *(float4*)(a + 4) = *(float4*)&As[kk][ty * 8 + 4];
            *(float4*)(b)     = *(float4*)&Bs[kk][tx * 8];
            *(float4*)(b + 4) = *(float4*)&Bs[kk][tx * 8 + 4];
            #pragma unroll
            for (int i = 0; i < 8; i++)
                #pragma unroll
                for (int j = 0; j < 8; j++)
                    acc[i][j] += a[i] * b[j];
        }
        __syncthreads();
    }

    #pragma unroll
    for (int i = 0; i < 8; i++) {
        int r = row0 + ty * 8 + i;
        if (r < NN) {
            #pragma unroll
            for (int j4 = 0; j4 < 2; j4++) {
                int cb = col0 + tx * 8 + j4 * 4;
                float4 bv = *(const float4*)&g_bias[cb];
                float4 v;
                v.x = acc[i][j4 * 4 + 0] + bv.x;
                v.y = acc[i][j4 * 4 + 1] + bv.y;
                v.z = acc[i][j4 * 4 + 2] + bv.z;
                v.w = acc[i][j4 * 4 + 3] + bv.w;
                *(float4*)&g_pre[(size_t)r * JDIM + cb] = v;
            }
        }
    }
}

// ---------------- gate math + output ----------------
__device__ __forceinline__ float fsigmoid(float x) {
    return 1.f / (1.f + __expf(-x));
}
__device__ __forceinline__ float ftanh(float x) {
    // tanh(x) = 2*sigmoid(2x) - 1
    float e = __expf(-2.f * x);
    return (1.f - e) / (1.f + e);
}

__global__ void k_gates(const float* __restrict__ c, const float* __restrict__ wc,
                        const float* __restrict__ b, float* __restrict__ out) {
    int idx = blockIdx.x * blockDim.x + threadIdx.x;
    if (idx >= NN * 256) return;
    int e = idx & 255;
    size_t o = (size_t)(idx >> 8) * 1024;
    float pi = g_pre[o + e];
    float pf = g_pre[o + 256 + e];
    float pc = g_pre[o + 512 + e];
    float po = g_pre[o + 768 + e];
    float cv = c[idx];
    float I  = fsigmoid(pi + wc[e] * cv + b[e]);
    float F  = fsigmoid(pf + wc[256 + e] * cv + b[256 + e]);
    float T  = ftanh(pc + b[512 + e]);
    float Cn = F * cv + I * T;
    float O  = fsigmoid(po + wc[512 + e] * Cn + b[768 + e]);
    float Hn = O * ftanh(Cn);
    out[idx]                 = O;
    out[NN * 256 + idx]      = Hn;
    out[2 * NN * 256 + idx]  = Cn;
}

// ---------------- launch ----------------
extern "C" void kernel_launch(void* const* d_in, const int* in_sizes, int n_in,
                              void* d_out, int out_size) {
    const float* X    = (const float*)d_in[0];
    const void*  ei   = d_in[1];
    const float* h    = (const float*)d_in[2];
    const float* c    = (const float*)d_in[3];
    const float* Wx_l = (const float*)d_in[4];
    const float* bx_l = (const float*)d_in[5];
    const float* Wx_r = (const float*)d_in[6];
    const float* Wh_l = (const float*)d_in[7];
    const float* bh_l = (const float*)d_in[8];
    const float* Wh_r = (const float*)d_in[9];
    const float* wc   = (const float*)d_in[10];
    const float* b    = (const float*)d_in[11];
    float* out = (float*)d_out;

    k_detect<<<1, 1>>>((const unsigned*)ei);
    k_convert<<<(EE + 255) / 256, 256>>>(ei);
    k_hist<<<(EE + 255) / 256, 256>>>();
    k_scan<<<1, 1024>>>();
    k_scatter<<<(EE + 255) / 256, 256>>>();
    k_agg<<<NN, 256>>>(X, h);
    k_packW<<<(KDIM * JDIM + 255) / 256, 256>>>(Wx_l, Wx_r, Wh_l, Wh_r, bx_l, bh_l);
    k_sgemm<<<dim3(JDIM / BN, (NN + BM - 1) / BM), 256>>>();
    k_gates<<<(NN * 256 + 255) / 256, 256>>>(c, wc, b, out);
}

// round 4
// speedup vs baseline: 2.4965x; 2.4965x over previous
#include <cuda_runtime.h>
#include <cuda_bf16.h>
#include <math.h>
#include <stdint.h>

#define NN 10000
#define EE 320000

// ---------------- scratch (static device globals; no allocation) ----------------
__device__ int   g_is64;
__device__ int   g_srcE[EE];
__device__ int   g_dstE[EE];
__device__ int   g_srcSorted[EE];
__device__ int   g_degi[NN];
__device__ int   g_cnt[NN];
__device__ int   g_off[NN + 1];
__device__ __nv_bfloat16 g_Ab[(size_t)NN * 2048];    // [hi(1024) | lo(1024)] per row
__device__ __nv_bfloat16 g_Wtb[(size_t)1024 * 2048]; // W^T: row j(out col), [hi(1024)|lo(1024)]
__device__ float g_bias[1024];
__device__ float g_pre[(size_t)NN * 1024];

__device__ __forceinline__ uint32_t smem_u32(const void* p) {
    uint32_t a;
    asm("{ .reg .u64 t; cvta.to.shared.u64 t, %1; cvt.u32.u64 %0, t; }" : "=r"(a) : "l"(p));
    return a;
}

// ---------------- edge dtype detection (int32 vs int64) ----------------
__global__ void k_detect(const unsigned* __restrict__ w) {
    unsigned bad = 0;
    #pragma unroll
    for (int i = 0; i < 64; i++) bad |= w[2 * i + 1];
    g_is64 = (bad == 0) ? 1 : 0;
}

__global__ void k_convert(const void* __restrict__ ei) {
    int e = blockIdx.x * blockDim.x + threadIdx.x;
    if (e < NN) { g_degi[e] = 0; g_cnt[e] = 0; }
    if (e >= EE) return;
    int src, dst;
    if (g_is64) {
        const long long* p = (const long long*)ei;
        src = (int)p[e]; dst = (int)p[EE + e];
    } else {
        const int* p = (const int*)ei;
        src = p[e]; dst = p[EE + e];
    }
    g_srcE[e] = src; g_dstE[e] = dst;
}

__global__ void k_hist() {
    int e = blockIdx.x * blockDim.x + threadIdx.x;
    if (e < EE) atomicAdd(&g_degi[g_dstE[e]], 1);
}

__global__ void k_scan() {
    __shared__ int s[1024];
    const int CH = (NN + 1023) / 1024;
    int t = threadIdx.x;
    int base = t * CH;
    int loc = 0;
    #pragma unroll
    for (int i = 0; i < CH; i++) { int idx = base + i; if (idx < NN) loc += g_degi[idx]; }
    s[t] = loc;
    __syncthreads();
    for (int off = 1; off < 1024; off <<= 1) {
        int v = (t >= off) ? s[t - off] : 0;
        __syncthreads();
        s[t] += v;
        __syncthreads();
    }
    int run = s[t] - loc;
    #pragma unroll
    for (int i = 0; i < CH; i++) {
        int idx = base + i;
        if (idx < NN) { g_off[idx] = run; run += g_degi[idx]; }
    }
    if (t == 1023) g_off[NN] = run;
}

__global__ void k_scatter() {
    int e = blockIdx.x * blockDim.x + threadIdx.x;
    if (e >= EE) return;
    int d = g_dstE[e];
    int pos = g_off[d] + atomicAdd(&g_cnt[d], 1);
    g_srcSorted[pos] = g_srcE[e];
}

// ---------------- aggregation + split-bf16 A packing ----------------
__device__ __forceinline__ void split_store(__nv_bfloat16* p, size_t hi_idx, float v) {
    __nv_bfloat16 hi = __float2bfloat16(v);
    float r = v - __bfloat162float(hi);
    p[hi_idx] = hi;
    p[hi_idx + 1024] = __float2bfloat16(r);
}

__global__ __launch_bounds__(256) void k_agg(const float* __restrict__ X,
                                             const float* __restrict__ h) {
    __shared__ int sidx[128];
    int n = blockIdx.x;
    int t = threadIdx.x;
    int s0 = g_off[n], s1 = g_off[n + 1];
    float sx = 0.f, sh = 0.f;
    for (int base = s0; base < s1; base += 128) {
        int cnt = min(128, s1 - base);
        if (t < cnt) sidx[t] = g_srcSorted[base + t];
        __syncthreads();
        for (int j = 0; j < cnt; j++) {
            int s = sidx[j];
            sx += X[s * 256 + t];
            sh += h[s * 256 + t];
        }
        __syncthreads();
    }
    int deg = s1 - s0;
    float inv = 1.f / (float)(deg > 0 ? deg : 1);
    size_t o = (size_t)n * 2048;
    split_store(g_Ab, o + t,       sx * inv);
    split_store(g_Ab, o + 256 + t, X[n * 256 + t]);
    split_store(g_Ab, o + 512 + t, sh * inv);
    split_store(g_Ab, o + 768 + t, h[n * 256 + t]);
}

// ---------------- weight packing (transposed, split bf16) ----------------
__global__ void k_packWt(const float* __restrict__ Wx_l, const float* __restrict__ Wx_r,
                         const float* __restrict__ Wh_l, const float* __restrict__ Wh_r,
                         const float* __restrict__ bx_l, const float* __restrict__ bh_l) {
    int idx = blockIdx.x * blockDim.x + threadIdx.x;
    if (idx >= 1024 * 1024) return;
    int d = idx & 1023;      // K row
    int j = idx >> 10;       // output col
    int k = j >> 8, e = j & 255;
    int seg = d >> 8, dd = d & 255;
    const float* src = (seg == 0) ? Wx_l : (seg == 1) ? Wx_r : (seg == 2) ? Wh_l : Wh_r;
    float w = src[k * 65536 + dd * 256 + e];
    split_store(g_Wtb, (size_t)j * 2048 + d, w);
    if (d == 0) g_bias[j] = bx_l[k * 256 + e] + bh_l[k * 256 + e];
}

// ---------------- mma.sync bf16 GEMM (split-bf16, 3 logical K segments) ----------------
#define BM 128
#define BN 128
#define BK 64
#define NITER 48   // 3 segments * 1024 / 64
#define TILE_B 16384
#define DYN_SMEM (4 * TILE_B)

#define LDSM_X4(r0, r1, r2, r3, addr) \
    asm volatile("ldmatrix.sync.aligned.m8n8.x4.shared.b16 {%0,%1,%2,%3}, [%4];" \
                 : "=r"(r0), "=r"(r1), "=r"(r2), "=r"(r3) : "r"(addr))

#define MMA16816(d, a0, a1, a2, a3, b0, b1) \
    asm volatile("mma.sync.aligned.m16n8k16.row.col.f32.bf16.bf16.f32 " \
                 "{%0,%1,%2,%3}, {%4,%5,%6,%7}, {%8,%9}, {%0,%1,%2,%3};" \
                 : "+f"((d)[0]), "+f"((d)[1]), "+f"((d)[2]), "+f"((d)[3]) \
                 : "r"(a0), "r"(a1), "r"(a2), "r"(a3), "r"(b0), "r"(b1))

__device__ __forceinline__ void issue_tile(uint32_t sA, uint32_t sB, int m0, int n0,
                                           int it, int tid) {
    int k0 = it * 64;
    int seg = k0 >> 10, kk = k0 & 1023;
    int acol = kk + (seg == 2 ? 1024 : 0);
    int bcol = kk + (seg == 1 ? 1024 : 0);
    #pragma unroll
    for (int i = 0; i < 4; i++) {
        int ch = tid + i * 256;
        int row = ch >> 3, c = ch & 7;
        uint32_t so = row * 128 + ((c ^ (row & 7)) << 4);
        const __nv_bfloat16* ga = g_Ab + (size_t)(m0 + row) * 2048 + acol + c * 8;
        unsigned sz = (m0 + row < NN) ? 16u : 0u;
        asm volatile("cp.async.cg.shared.global [%0], [%1], 16, %2;"
                     :: "r"(sA + so), "l"(ga), "r"(sz));
        const __nv_bfloat16* gb = g_Wtb + (size_t)(n0 + row) * 2048 + bcol + c * 8;
        asm volatile("cp.async.cg.shared.global [%0], [%1], 16;"
                     :: "r"(sB + so), "l"(gb));
    }
}

__global__ __launch_bounds__(256) void k_mma() {
    extern __shared__ char smem[];
    uint32_t sb = smem_u32(smem);
    int tid = threadIdx.x;
    int lane = tid & 31, wid = tid >> 5;
    int warp_m = wid & 3, warp_n = wid >> 2;
    int m0 = blockIdx.y * BM, n0 = blockIdx.x * BN;

    float acc[2][8][4];
    #pragma unroll
    for (int i = 0; i < 2; i++)
        #pragma unroll
        for (int j = 0; j < 8; j++)
            #pragma unroll
            for (int r = 0; r < 4; r++) acc[i][j][r] = 0.f;

    uint32_t sA[2] = { sb, sb + 2 * TILE_B };
    uint32_t sB[2] = { sb + TILE_B, sb + 3 * TILE_B };

    issue_tile(sA[0], sB[0], m0, n0, 0, tid);
    asm volatile("cp.async.commit_group;" ::: "memory");
    issue_tile(sA[1], sB[1], m0, n0, 1, tid);
    asm volatile("cp.async.commit_group;" ::: "memory");

    // ldmatrix address invariants
    int rowA[2], rowA7[2];
    #pragma unroll
    for (int mi = 0; mi < 2; mi++) {
        int r = warp_m * 32 + mi * 16 + (lane & 15);
        rowA[mi] = r * 128;
        rowA7[mi] = r & 7;
    }
    int achk = lane >> 4;             // 0/1: k chunk offset for A
    int local = lane & 7, quad = lane >> 3;
    int bchk = quad & 1;              // k chunk offset for B
    int rowB[4], rowB7[4];
    #pragma unroll
    for (int np = 0; np < 4; np++) {
        int r = warp_n * 64 + np * 16 + ((quad >> 1) << 3) + local;
        rowB[np] = r * 128;
        rowB7[np] = r & 7;
    }

    for (int it = 0; it < NITER; it++) {
        asm volatile("cp.async.wait_group 1;" ::: "memory");
        __syncthreads();
        int buf = it & 1;
        uint32_t Ab = sA[buf], Bb = sB[buf];
        #pragma unroll
        for (int ks = 0; ks < 4; ks++) {
            uint32_t a[2][4];
            #pragma unroll
            for (int mi = 0; mi < 2; mi++) {
                uint32_t ad = Ab + rowA[mi] + ((((ks * 2 + achk)) ^ rowA7[mi]) << 4);
                LDSM_X4(a[mi][0], a[mi][1], a[mi][2], a[mi][3], ad);
            }
            #pragma unroll
            for (int np = 0; np < 4; np++) {
                uint32_t bd = Bb + rowB[np] + ((((ks * 2 + bchk)) ^ rowB7[np]) << 4);
                uint32_t t0, t1, t2, t3;
                LDSM_X4(t0, t1, t2, t3, bd);
                MMA16816(acc[0][np * 2],     a[0][0], a[0][1], a[0][2], a[0][3], t0, t1);
                MMA16816(acc[1][np * 2],     a[1][0], a[1][1], a[1][2], a[1][3], t0, t1);
                MMA16816(acc[0][np * 2 + 1], a[0][0], a[0][1], a[0][2], a[0][3], t2, t3);
                MMA16816(acc[1][np * 2 + 1], a[1][0], a[1][1], a[1][2], a[1][3], t2, t3);
            }
        }
        __syncthreads();
        if (it + 2 < NITER) issue_tile(sA[buf], sB[buf], m0, n0, it + 2, tid);
        asm volatile("cp.async.commit_group;" ::: "memory");
    }

    // epilogue: bias + direct stores
    int g = lane >> 2, t4 = lane & 3;
    #pragma unroll
    for (int mi = 0; mi < 2; mi++) {
        #pragma unroll
        for (int half = 0; half < 2; half++) {
            int r = m0 + warp_m * 32 + mi * 16 + g + half * 8;
            if (r < NN) {
                #pragma unroll
                for (int ni = 0; ni < 8; ni++) {
                    int col = n0 + warp_n * 64 + ni * 8 + t4 * 2;
                    float2 bv = *(const float2*)&g_bias[col];
                    float2 v;
                    v.x = acc[mi][ni][half * 2 + 0] + bv.x;
                    v.y = acc[mi][ni][half * 2 + 1] + bv.y;
                    *(float2*)&g_pre[(size_t)r * 1024 + col] = v;
                }
            }
        }
    }
}

// ---------------- gate math + output ----------------
__device__ __forceinline__ float fsigmoid(float x) { return 1.f / (1.f + __expf(-x)); }
__device__ __forceinline__ float ftanh(float x) {
    float e = __expf(-2.f * x);
    return (1.f - e) / (1.f + e);
}

__global__ void k_gates(const float* __restrict__ c, const float* __restrict__ wc,
                        const float* __restrict__ b, float* __restrict__ out) {
    int idx = blockIdx.x * blockDim.x + threadIdx.x;
    if (idx >= NN * 256) return;
    int e = idx & 255;
    size_t o = (size_t)(idx >> 8) * 1024;
    float pi = g_pre[o + e];
    float pf = g_pre[o + 256 + e];
    float pc = g_pre[o + 512 + e];
    float po = g_pre[o + 768 + e];
    float cv = c[idx];
    float I  = fsigmoid(pi + wc[e] * cv + b[e]);
    float F  = fsigmoid(pf + wc[256 + e] * cv + b[256 + e]);
    float T  = ftanh(pc + b[512 + e]);
    float Cn = F * cv + I * T;
    float O  = fsigmoid(po + wc[512 + e] * Cn + b[768 + e]);
    float Hn = O * ftanh(Cn);
    out[idx]                = O;
    out[NN * 256 + idx]     = Hn;
    out[2 * NN * 256 + idx] = Cn;
}

// ---------------- launch ----------------
extern "C" void kernel_launch(void* const* d_in, const int* in_sizes, int n_in,
                              void* d_out, int out_size) {
    const float* X    = (const float*)d_in[0];
    const void*  ei   = d_in[1];
    const float* h    = (const float*)d_in[2];
    const float* c    = (const float*)d_in[3];
    const float* Wx_l = (const float*)d_in[4];
    const float* bx_l = (const float*)d_in[5];
    const float* Wx_r = (const float*)d_in[6];
    const float* Wh_l = (const float*)d_in[7];
    const float* bh_l = (const float*)d_in[8];
    const float* Wh_r = (const float*)d_in[9];
    const float* wc   = (const float*)d_in[10];
    const float* b    = (const float*)d_in[11];
    float* out = (float*)d_out;

    static int smem_set = 0;
    if (!smem_set) {
        cudaFuncSetAttribute(k_mma, cudaFuncAttributeMaxDynamicSharedMemorySize, DYN_SMEM);
        smem_set = 1;
    }

    k_detect<<<1, 1>>>((const unsigned*)ei);
    k_convert<<<(EE + 255) / 256, 256>>>(ei);
    k_hist<<<(EE + 255) / 256, 256>>>();
    k_scan<<<1, 1024>>>();
    k_scatter<<<(EE + 255) / 256, 256>>>();
    k_agg<<<NN, 256>>>(X, h);
    k_packWt<<<(1024 * 1024 + 255) / 256, 256>>>(Wx_l, Wx_r, Wh_l, Wh_r, bx_l, bh_l);
    k_mma<<<dim3(8, 79), 256, DYN_SMEM>>>();
    k_gates<<<(NN * 256 + 255) / 256, 256>>>(c, wc, b, out);
}